// round 7
// baseline (speedup 1.0000x reference)
#include <cuda_runtime.h>

#define IN_DIM  1024
#define OUT_DIM 512
#define B_DIM   128
#define OT      16                  // output tile per block
#define ICH     32                  // input chunk per block
#define NSPLIT  (IN_DIM / ICH)      // 32 partials per (b,o)
#define NOUT    (B_DIM * OUT_DIM)   // 65536

// Partial sums: [split][b][o]  (32 * 128 * 512 * 4B = 8 MB)
__device__ float g_part[NSPLIT * B_DIM * OUT_DIM];

__device__ __forceinline__ float tanh_approx(float x) {
    float y;
    asm("tanh.approx.f32 %0, %1;" : "=f"(y) : "f"(x));
    return y;
}
__device__ __forceinline__ float rcp_approx(float x) {
    float y;
    asm("rcp.approx.f32 %0, %1;" : "=f"(y) : "f"(x));
    return y;
}

__device__ __forceinline__ float weff_one(float4 t, float w) {
    float a = __expf(t.x), b = __expf(t.y), c = __expf(t.z), d = __expf(t.w);
    float inv = rcp_approx(a + b + c + d);
    return (b * w + c * tanh_approx(w) + d * __sinf(w)) * inv;
}

// Fused kernel: each block owns (o-tile 16, i-chunk 32, ALL 128 batches).
// 1) computes its 16x32 W_eff tile (each element exactly once, chip-wide)
// 2) stages the 128x32 x tile
// 3) partial[split][b][o] = sum_{i in chunk} tanh(x[b,i] * W_eff[o,i])
__global__ __launch_bounds__(256, 7)
void fbn_fused_kernel(const float* __restrict__ x,
                      const float* __restrict__ W,
                      const float* __restrict__ theta) {
    __shared__ float ws_t[ICH][OT];          // W_eff transposed [i][o], 2 KB
    __shared__ float xs[B_DIM][ICH];         // x tile [b][i], 16 KB

    const int tid = threadIdx.x;
    const int o0 = blockIdx.x * OT;
    const int c0 = blockIdx.y * ICH;

    // ---- W_eff tile: 512 elements, 2 per thread (m = tid, tid+256) ----
    {
        const float4* t4 = reinterpret_cast<const float4*>(theta);
        int m0 = tid, m1 = tid + 256;
        int ol0 = m0 >> 5, il0 = m0 & 31;
        int ol1 = m1 >> 5, il1 = m1 & 31;
        int g0 = (o0 + ol0) * IN_DIM + c0 + il0;
        int g1 = (o0 + ol1) * IN_DIM + c0 + il1;
        float4 ta = t4[g0];
        float4 tb = t4[g1];
        float wa = W[g0];
        float wb = W[g1];
        ws_t[il0][ol0] = weff_one(ta, wa);
        ws_t[il1][ol1] = weff_one(tb, wb);
    }

    // ---- x tile: 128 rows x 8 float4 = 1024 float4, 4 per thread ----
    {
        const float4* xg = reinterpret_cast<const float4*>(x);
        #pragma unroll
        for (int k = 0; k < 4; k++) {
            int f = tid + k * 256;
            int row = f >> 3, col = f & 7;
            float4 v = xg[row * (IN_DIM / 4) + (c0 >> 2) + col];
            *reinterpret_cast<float4*>(&xs[row][col * 4]) = v;
        }
    }
    __syncthreads();

    // ---- compute: thread = (o = tx, batches ty*8 .. ty*8+7) ----
    const int tx = tid & 15;
    const int ty = tid >> 4;
    const float* xrow = &xs[ty * 8][0];

    float acc0 = 0.f, acc1 = 0.f, acc2 = 0.f, acc3 = 0.f;
    float acc4 = 0.f, acc5 = 0.f, acc6 = 0.f, acc7 = 0.f;

    #pragma unroll 8
    for (int i = 0; i < ICH; i++) {
        float w = ws_t[i][tx];
        acc0 += tanh_approx(xrow[0 * ICH + i] * w);
        acc1 += tanh_approx(xrow[1 * ICH + i] * w);
        acc2 += tanh_approx(xrow[2 * ICH + i] * w);
        acc3 += tanh_approx(xrow[3 * ICH + i] * w);
        acc4 += tanh_approx(xrow[4 * ICH + i] * w);
        acc5 += tanh_approx(xrow[5 * ICH + i] * w);
        acc6 += tanh_approx(xrow[6 * ICH + i] * w);
        acc7 += tanh_approx(xrow[7 * ICH + i] * w);
    }

    float* dst = g_part + (blockIdx.y * B_DIM + ty * 8) * OUT_DIM + o0 + tx;
    dst[0 * OUT_DIM] = acc0;
    dst[1 * OUT_DIM] = acc1;
    dst[2 * OUT_DIM] = acc2;
    dst[3 * OUT_DIM] = acc3;
    dst[4 * OUT_DIM] = acc4;
    dst[5 * OUT_DIM] = acc5;
    dst[6 * OUT_DIM] = acc6;
    dst[7 * OUT_DIM] = acc7;
}

// Reduce: out[b][o] = bias[o] + sum_s partial[s][b][o]
// All 32 loads issued independently (MLP=32), then tree-summed.
__global__ void reduce_kernel(const float* __restrict__ bias,
                              float* __restrict__ out) {
    int idx = blockIdx.x * blockDim.x + threadIdx.x;   // 0..65535
    const float* p = g_part + idx;

    float v0  = p[ 0 * NOUT], v1  = p[ 1 * NOUT], v2  = p[ 2 * NOUT], v3  = p[ 3 * NOUT];
    float v4  = p[ 4 * NOUT], v5  = p[ 5 * NOUT], v6  = p[ 6 * NOUT], v7  = p[ 7 * NOUT];
    float v8  = p[ 8 * NOUT], v9  = p[ 9 * NOUT], v10 = p[10 * NOUT], v11 = p[11 * NOUT];
    float v12 = p[12 * NOUT], v13 = p[13 * NOUT], v14 = p[14 * NOUT], v15 = p[15 * NOUT];
    float v16 = p[16 * NOUT], v17 = p[17 * NOUT], v18 = p[18 * NOUT], v19 = p[19 * NOUT];
    float v20 = p[20 * NOUT], v21 = p[21 * NOUT], v22 = p[22 * NOUT], v23 = p[23 * NOUT];
    float v24 = p[24 * NOUT], v25 = p[25 * NOUT], v26 = p[26 * NOUT], v27 = p[27 * NOUT];
    float v28 = p[28 * NOUT], v29 = p[29 * NOUT], v30 = p[30 * NOUT], v31 = p[31 * NOUT];
    float bb = bias[idx & (OUT_DIM - 1)];

    // Tree sum (independent adds, no long serial chain).
    v0  += v1;  v2  += v3;  v4  += v5;  v6  += v7;
    v8  += v9;  v10 += v11; v12 += v13; v14 += v15;
    v16 += v17; v18 += v19; v20 += v21; v22 += v23;
    v24 += v25; v26 += v27; v28 += v29; v30 += v31;
    v0  += v2;  v4  += v6;  v8  += v10; v12 += v14;
    v16 += v18; v20 += v22; v24 += v26; v28 += v30;
    v0  += v4;  v8  += v12; v16 += v20; v24 += v28;
    v0  += v8;  v16 += v24;
    out[idx] = bb + v0 + v16;
}

extern "C" void kernel_launch(void* const* d_in, const int* in_sizes, int n_in,
                              void* d_out, int out_size) {
    const float* x     = (const float*)d_in[0];   // (128, 1024)
    const float* W     = (const float*)d_in[1];   // (512, 1024)
    const float* bias  = (const float*)d_in[2];   // (512,)
    const float* theta = (const float*)d_in[3];   // (512, 1024, 4)
    float* out = (float*)d_out;                   // (128, 512)

    (void)in_sizes; (void)n_in; (void)out_size;

    dim3 grid(OUT_DIM / OT, IN_DIM / ICH);   // (32, 32) = 1024 blocks, 1 wave @ 7/SM
    fbn_fused_kernel<<<grid, 256>>>(x, W, theta);

    reduce_kernel<<<NOUT / 256, 256>>>(bias, out);
}